// round 8
// baseline (speedup 1.0000x reference)
#include <cuda_runtime.h>
#include <cstdint>

// Problem constants
#define BB 8
#define TT 128
#define CL 16
#define NTHREADS 512

// Output layout (float32, concatenated): outputs[8,128,256], seq_lengths[8],
// hidden[1,8,256], attn[8,128,128]
#define SEQ_OFF     262144
#define HID_OFF     262152
#define ATTN_OFF    264200

// Device scratch: xw1 = x @ W1[:, :E]^T + b1 -> [B*T, 512]; wx = x @ Wih^T -> [B*T, 1024]
__device__ float g_xw1[1024 * 512];
__device__ float g_wx[1024 * 1024];

// ---------------- SMEM layout (float offsets) ----------------
#define OFF_W1H   0        // [32][256]  W1 h-cols, my 32 k rows
#define OFF_WHH   8192     // [64][256]  Whh rows for my 64 gate rows
#define OFF_WX    24576    // [128][68]  Wx[j][my 64 gate rows] (pitch 68)
#define OFF_HBUF  33280    // [256]  h assembled locally via pulls
#define OFF_EP    33536    // [16][128]  energy partials (hub assembly area)
#define OFF_HPST  35584    // [32]   my hproj slice
#define OFF_HWST  35616    // [64]   my h@Whh rows
#define OFF_BIAS  35680    // [64]
#define OFF_PST   35744    // [128]  my energy partials (512B bulk src, peers only)
#define OFF_WB    35872    // [128]  softmax weights (hub computes; peers pull)
#define OFF_GFIN  36000    // [64]   activated gates
#define OFF_CST   36064    // [16]   cell state
#define OFF_HST   36080    // [2][16] h_new chunk (pulled by peers)
#define OFF_SRED  36112    // [16]   softmax-sum warp partials
#define OFF_MBAR  36128    // 3 mbarriers x 8B: h(+0), ered(+8), wsig(+16)
#define SMEM_FLOATS 36136
#define SMEM_BYTES (SMEM_FLOATS * 4)

// ---------------- helpers ----------------
__device__ __forceinline__ unsigned crank() {
    unsigned r; asm("mov.u32 %0, %%cluster_ctarank;" : "=r"(r)); return r;
}
__device__ __forceinline__ uint32_t smem_u32(const void* p) {
    uint32_t a;
    asm("{ .reg .u64 t; cvta.to.shared.u64 t, %1; cvt.u32.u64 %0, t; }" : "=r"(a) : "l"(p));
    return a;
}
__device__ __forceinline__ uint32_t mapa_(uint32_t a, int peer) {
    uint32_t r;
    asm("mapa.shared::cluster.u32 %0, %1, %2;" : "=r"(r) : "r"(a), "r"(peer));
    return r;
}
// bulk DSMEM copy: local smem -> peer smem, completes peer's mbarrier by tx bytes
__device__ __forceinline__ void bulk_s2c(uint32_t rdst, uint32_t lsrc, uint32_t bytes,
                                         uint32_t rmbar) {
    asm volatile(
        "cp.async.bulk.shared::cluster.shared::cta.mbarrier::complete_tx::bytes "
        "[%0], [%1], %2, [%3];"
        :: "r"(rdst), "r"(lsrc), "r"(bytes), "r"(rmbar) : "memory");
}
__device__ __forceinline__ void fence_async_cta() {
    asm volatile("fence.proxy.async.shared::cta;" ::: "memory");
}
__device__ __forceinline__ void mbar_init(uint32_t mb, uint32_t cnt) {
    asm volatile("mbarrier.init.shared.b64 [%0], %1;" :: "r"(mb), "r"(cnt) : "memory");
}
__device__ __forceinline__ void mbar_arm(uint32_t mb, uint32_t tx) {
    asm volatile("mbarrier.arrive.expect_tx.shared.b64 _, [%0], %1;" :: "r"(mb), "r"(tx) : "memory");
}
// payload-free remote arrive (release at cluster scope) on peer's mbarrier
__device__ __forceinline__ void arrive_remote(uint32_t mb_local, int peer) {
    uint32_t ra = mapa_(mb_local, peer);
    asm volatile("mbarrier.arrive.release.cluster.shared::cluster.b64 _, [%0];"
                 :: "r"(ra) : "memory");
}
// remote shared-memory vector load (pull model)
__device__ __forceinline__ float4 ldsc4(uint32_t ra) {
    float4 v;
    asm volatile("ld.shared::cluster.v4.f32 {%0,%1,%2,%3}, [%4];"
                 : "=f"(v.x), "=f"(v.y), "=f"(v.z), "=f"(v.w) : "r"(ra));
    return v;
}
// cta-scope acquire wait (hub's local tx barrier: complete_tx publishes data)
__device__ __forceinline__ void mwait(uint32_t mb, uint32_t ph) {
    uint32_t done = 0;
    do {
        asm volatile("{\n\t.reg .pred p;\n\t"
                     "mbarrier.try_wait.parity.acquire.cta.shared::cta.b64 p, [%1], %2, 0x989680;\n\t"
                     "selp.b32 %0, 1, 0, p;\n\t}"
                     : "=r"(done) : "r"(mb), "r"(ph) : "memory");
    } while (!done);
}
// cluster-scope acquire wait (we read peers' SMEM after this)
__device__ __forceinline__ void mwait_cl(uint32_t mb, uint32_t ph) {
    uint32_t done = 0;
    do {
        asm volatile("{\n\t.reg .pred p;\n\t"
                     "mbarrier.try_wait.parity.acquire.cluster.shared::cta.b64 p, [%1], %2, 0x989680;\n\t"
                     "selp.b32 %0, 1, 0, p;\n\t}"
                     : "=r"(done) : "r"(mb), "r"(ph) : "memory");
    } while (!done);
}
__device__ __forceinline__ float wsum(float v) {
    #pragma unroll
    for (int o = 16; o > 0; o >>= 1) v += __shfl_xor_sync(0xffffffffu, v, o);
    return v;
}
#define CLUSTER_SYNC() do { \
    asm volatile("barrier.cluster.arrive.aligned;" ::: "memory"); \
    asm volatile("barrier.cluster.wait.aligned;"   ::: "memory"); \
} while (0)

// ---- 2-MUFU tanh: e = exp(2x); (e-1)/(e+1). ~1e-6 accurate ----
__device__ __forceinline__ float tanh_m(float x) {
    x = fminf(fmaxf(x, -9.f), 9.f);
    float e = __expf(2.f * x);
    return __fdividef(e - 1.f, e + 1.f);
}
__device__ __forceinline__ float sigmoid_m(float x) {
    return __fdividef(1.f, 1.f + __expf(-x));
}

// ---------------- precompute GEMMs ----------------
template <int NOUT, bool HASB>
__global__ void nt_gemm(const float* __restrict__ X, const float* __restrict__ W,
                        const float* __restrict__ bias, float* __restrict__ outp) {
    __shared__ float As[64][33];
    __shared__ float Bs[64][33];
    const int m0 = blockIdx.x * 64, n0 = blockIdx.y * 64;
    const int tx = threadIdx.x, ty = threadIdx.y;
    const int tid = ty * 16 + tx;
    float acc[4][4] = {};
    for (int kt = 0; kt < 256; kt += 32) {
        for (int idx = tid; idx < 64 * 32; idx += 256) {
            int rr = idx >> 5, kk = idx & 31;
            As[rr][kk] = X[(m0 + rr) * 256 + kt + kk];
            Bs[rr][kk] = W[(size_t)(n0 + rr) * 256 + kt + kk];
        }
        __syncthreads();
        #pragma unroll
        for (int kk = 0; kk < 32; kk++) {
            float a[4], bv[4];
            #pragma unroll
            for (int i = 0; i < 4; i++) { a[i] = As[ty*4+i][kk]; bv[i] = Bs[tx*4+i][kk]; }
            #pragma unroll
            for (int i = 0; i < 4; i++)
                #pragma unroll
                for (int j = 0; j < 4; j++) acc[i][j] += a[i] * bv[j];
        }
        __syncthreads();
    }
    #pragma unroll
    for (int i = 0; i < 4; i++)
        #pragma unroll
        for (int j = 0; j < 4; j++) {
            int n = n0 + tx*4 + j;
            float v = acc[i][j];
            if (HASB) v += bias[n];
            outp[(size_t)(m0 + ty*4 + i) * NOUT + n] = v;
        }
}

__global__ void xw1_gemm(const float* __restrict__ X, const float* __restrict__ W1,
                         const float* __restrict__ b1) {
    __shared__ float As[64][33];
    __shared__ float Bs[64][33];
    const int m0 = blockIdx.x * 64, n0 = blockIdx.y * 64;
    const int tx = threadIdx.x, ty = threadIdx.y;
    const int tid = ty * 16 + tx;
    float acc[4][4] = {};
    for (int kt = 0; kt < 256; kt += 32) {
        for (int idx = tid; idx < 64 * 32; idx += 256) {
            int rr = idx >> 5, kk = idx & 31;
            As[rr][kk] = X[(m0 + rr) * 256 + kt + kk];
            Bs[rr][kk] = W1[(size_t)(n0 + rr) * 512 + kt + kk];
        }
        __syncthreads();
        #pragma unroll
        for (int kk = 0; kk < 32; kk++) {
            float a[4], bv[4];
            #pragma unroll
            for (int i = 0; i < 4; i++) { a[i] = As[ty*4+i][kk]; bv[i] = Bs[tx*4+i][kk]; }
            #pragma unroll
            for (int i = 0; i < 4; i++)
                #pragma unroll
                for (int j = 0; j < 4; j++) acc[i][j] += a[i] * bv[j];
        }
        __syncthreads();
    }
    #pragma unroll
    for (int i = 0; i < 4; i++)
        #pragma unroll
        for (int j = 0; j < 4; j++) {
            int n = n0 + tx*4 + j;
            g_xw1[(size_t)(m0 + ty*4 + i) * 512 + n] = acc[i][j] + b1[n];
        }
}

// ---------------- persistent recurrence: hub-and-spoke, 1 bulk copy/CTA/step ----------------
__global__ void __launch_bounds__(NTHREADS, 1)
lstm_attn(const float* __restrict__ x, const int* __restrict__ seqlen,
          const float* __restrict__ W1, const float* __restrict__ W2,
          const float* __restrict__ b2w, const float* __restrict__ Whh,
          const float* __restrict__ bih, const float* __restrict__ bhh,
          float* __restrict__ out) {
    extern __shared__ float sm[];
    const int tid = threadIdx.x;
    const int w = tid >> 5, lane = tid & 31;
    const int r = (int)crank();
    const int b = blockIdx.x >> 4;
    const int len = seqlen[b];
    const float b2v = b2w[0];
    const uint32_t smb = smem_u32(sm);
    const uint32_t MB_H = smb + 4u * OFF_MBAR;        // count-16 h-ready
    const uint32_t MB_E = MB_H + 8u;                  // hub: tx barrier for EP pushes
    const uint32_t MB_W = MB_H + 16u;                 // count-1 WB-ready signal

    // ---- prologue: weight slices ----
    for (int idx = tid; idx < 32 * 256; idx += NTHREADS) {          // W1 h-cols, k rows [32r,32r+32)
        int row = idx >> 8, d = idx & 255;
        sm[OFF_W1H + idx] = W1[(size_t)(32 * r + row) * 512 + 256 + d];
    }
    for (int idx = tid; idx < 64 * 256; idx += NTHREADS) {          // Whh rows for my gates
        int q = idx >> 8, d = idx & 255;
        int gate = q >> 4, i = q & 15;
        sm[OFF_WHH + idx] = Whh[(size_t)(gate * 256 + 16 * r + i) * 256 + d];
    }
    for (int idx = tid; idx < 128 * 64; idx += NTHREADS) {          // Wx[j][my 64 rows], pitch 68
        int j = idx >> 6, q = idx & 63;
        sm[OFF_WX + j * 68 + q] =
            g_wx[(size_t)(b * 128 + j) * 1024 + ((q >> 4) << 8) + 16 * r + (q & 15)];
    }
    if (tid < 64) {
        int gate = tid >> 4, i = tid & 15;
        int row = gate * 256 + 16 * r + i;
        sm[OFF_BIAS + tid] = bih[row] + bhh[row];
        sm[OFF_HWST + tid] = 0.f;                      // t=0: h=0 -> h@Whh = 0
    }
    if (tid < 32) { sm[OFF_HPST + tid] = 0.f; sm[OFF_HST + tid] = 0.f; }
    if (tid < 16) sm[OFF_CST + tid] = 0.f;
    if (r == 0 && tid == 0) out[SEQ_OFF + b] = (float)len;

    // per-thread loop-invariant registers: my 8 xw1 values and 8 W2 values
    const int jE = tid >> 2, qE = tid & 3;
    float xwr[8], w2r[8];
    {
        const float* src = g_xw1 + (size_t)(b * 128 + jE) * 512 + 32 * r + qE * 8;
        const float* w2s = W2 + 32 * r + qE * 8;
        #pragma unroll
        for (int i = 0; i < 8; i++) { xwr[i] = src[i]; w2r[i] = w2s[i]; }
    }

    if (tid == 0) {
        mbar_init(MB_H, 16);   // 16 arrivals (all CTAs incl. self)
        mbar_init(MB_E, 1);    // arm-arrival + tx
        mbar_init(MB_W, 1);    // hub's single remote arrive
        asm volatile("fence.mbarrier_init.release.cluster;" ::: "memory");
        if (r == 0) mbar_arm(MB_E, 15 * 512);   // ered for t=0 (15 peer pushes)
    }
    __syncthreads();
    CLUSTER_SYNC();   // mbarrier inits (+hub arm) visible before any remote traffic

    for (int t = 0; t < TT; t++) {
        const bool active = t < len;

        // ---- h phase (t>=1): wait 16 signals, pull peers' h chunks, compute P1 ----
        if (t > 0) {
            mwait_cl(MB_H, (t - 1) & 1);
            if (tid < 64) {
                int peer = tid >> 2, part = tid & 3;
                float4 v = ldsc4(mapa_(smb + 4u * (OFF_HST + (t & 1) * 16 + part * 4), peer));
                *(float4*)(sm + OFF_HBUF + peer * 16 + part * 4) = v;
            }
            __syncthreads();
            // P1: hproj (32 rows) + h@Whh (64 rows): 16 warps x 6 rows
            const float* hb = sm + OFF_HBUF;
            float4 h0 = *(const float4*)(hb + lane * 8);
            float4 h1 = *(const float4*)(hb + lane * 8 + 4);
            #pragma unroll
            for (int rr = 0; rr < 6; rr++) {
                int row = w * 6 + rr;
                const float* wr = (row < 32) ? (sm + OFF_W1H + row * 256)
                                             : (sm + OFF_WHH + (row - 32) * 256);
                float4 a0 = *(const float4*)(wr + lane * 8);
                float4 a1 = *(const float4*)(wr + lane * 8 + 4);
                float acc = a0.x*h0.x + a0.y*h0.y + a0.z*h0.z + a0.w*h0.w
                          + a1.x*h1.x + a1.y*h1.y + a1.z*h1.z + a1.w*h1.w;
                acc = wsum(acc);
                if (lane == 0) {
                    if (row < 32) sm[OFF_HPST + row] = acc;
                    else          sm[OFF_HWST + row - 32] = acc;
                }
            }
            __syncthreads();
        }

        // ---- P2: energy partials (8 tanh/thread); hub writes own EP row directly ----
        {
            const float4* hp4 = (const float4*)(sm + OFF_HPST + qE * 8);
            float4 hpa = hp4[0], hpb = hp4[1];
            const float hp[8] = {hpa.x, hpa.y, hpa.z, hpa.w, hpb.x, hpb.y, hpb.z, hpb.w};
            float acc = 0.f;
            #pragma unroll
            for (int i = 0; i < 8; i++)
                acc = fmaf(tanh_m(xwr[i] + hp[i]), w2r[i], acc);
            acc += __shfl_xor_sync(0xffffffffu, acc, 1);
            acc += __shfl_xor_sync(0xffffffffu, acc, 2);
            if (qE == 0) sm[(r == 0 ? OFF_EP : OFF_PST) + jE] = acc;
        }
        __syncthreads();
        if (r != 0 && tid == 0) {            // ONE bulk push to hub
            fence_async_cta();
            bulk_s2c(mapa_(smb + 4u * (OFF_EP + r * 128), 0),
                     smb + 4u * OFF_PST, 512, mapa_(MB_E, 0));
        }

        // ---- P3: hub reduces + softmax + attn write + signal; peers pull WB ----
        if (r == 0) {
            mwait(MB_E, t & 1);
            if (tid == 0) mbar_arm(MB_E, 15 * 512);   // arm for t+1 (pushes gated on wsig below)
            float ex = 0.f;
            {
                const float* epb = sm + OFF_EP;
                float s = epb[(4*qE + 0) * 128 + jE] + epb[(4*qE + 1) * 128 + jE]
                        + epb[(4*qE + 2) * 128 + jE] + epb[(4*qE + 3) * 128 + jE];
                s += __shfl_xor_sync(0xffffffffu, s, 1);
                s += __shfl_xor_sync(0xffffffffu, s, 2);
                if (qE == 0)
                    ex = (jE < len) ? __expf(tanh_m(s + b2v)) : 0.f;  // energies in [-1,1]
            }
            float wp = wsum(ex);
            if (lane == 0) sm[OFF_SRED + w] = wp;
            __syncthreads();
            {
                const float4* sr = (const float4*)(sm + OFF_SRED);
                float4 a = sr[0], c = sr[1], d = sr[2], e4 = sr[3];
                float S = (a.x+a.y+a.z+a.w) + (c.x+c.y+c.z+c.w)
                        + (d.x+d.y+d.z+d.w) + (e4.x+e4.y+e4.z+e4.w);
                float Sinv = __fdividef(1.f, S);
                if (qE == 0) {
                    float wv = active ? ex * Sinv : 0.f;
                    sm[OFF_WB + jE] = wv;
                    out[ATTN_OFF + (size_t)(b * 128 + t) * 128 + jE] = wv;  // hub writes full row
                }
            }
            __syncthreads();
            if (tid < 15) arrive_remote(MB_W, tid + 1);
        } else {
            mwait_cl(MB_W, t & 1);
            if (tid < 32) {
                float4 v = ldsc4(mapa_(smb + 4u * (OFF_WB + tid * 4), 0));
                *(float4*)(sm + OFF_WB + tid * 4) = v;
            }
            __syncthreads();
        }

        // ---- P4: gates from Wx: row q = tid>>3, jq = tid&7 ----
        {
            int q = tid >> 3, jq = tid & 7;
            const float* wx = sm + OFF_WX + q;
            float acc = 0.f;
            #pragma unroll
            for (int jj = 0; jj < 16; jj++) {
                int j = jq + 8 * jj;
                acc = fmaf(sm[OFF_WB + j], wx[j * 68], acc);
            }
            acc += __shfl_xor_sync(0xffffffffu, acc, 1);
            acc += __shfl_xor_sync(0xffffffffu, acc, 2);
            acc += __shfl_xor_sync(0xffffffffu, acc, 4);
            if (jq == 0) {
                acc += sm[OFF_HWST + q] + sm[OFF_BIAS + q];
                sm[OFF_GFIN + q] = ((q >> 4) == 2) ? tanh_m(acc) : sigmoid_m(acc);
            }
        }
        __syncthreads();

        // ---- P5: LSTM update; write outputs; stage HST; signal h(t+1) ----
        if (tid < 16) {
            float c = sm[OFF_GFIN + 16 + tid] * sm[OFF_CST + tid]
                    + sm[OFF_GFIN + tid] * sm[OFF_GFIN + 32 + tid];
            sm[OFF_CST + tid] = c;
            float hn = sm[OFF_GFIN + 48 + tid] * tanh_m(c);
            out[(size_t)(b * 128 + t) * 256 + 16 * r + tid] = active ? hn : 0.f;
            if (t == len - 1) out[HID_OFF + b * 256 + 16 * r + tid] = hn;
            sm[OFF_HST + ((t + 1) & 1) * 16 + tid] = hn;
        }
        __syncthreads();
        if (t < TT - 1 && tid < 16) arrive_remote(MB_H, tid);  // signal all (incl. self)
    }

    // peers may still be pulling from my SMEM on the final step — hold the cluster
    CLUSTER_SYNC();
}

// ---------------- host launch ----------------
extern "C" void kernel_launch(void* const* d_in, const int* in_sizes, int n_in,
                              void* d_out, int out_size) {
    const float* x   = (const float*)d_in[0];
    const int*   sl  = (const int*)  d_in[1];
    const float* W1  = (const float*)d_in[2];
    const float* b1  = (const float*)d_in[3];
    const float* W2  = (const float*)d_in[4];
    const float* b2  = (const float*)d_in[5];
    const float* Wih = (const float*)d_in[6];
    const float* Whh = (const float*)d_in[7];
    const float* bih = (const float*)d_in[8];
    const float* bhh = (const float*)d_in[9];
    float* out = (float*)d_out;

    xw1_gemm<<<dim3(16, 8), dim3(16, 16)>>>(x, W1, b1);
    {
        float* gwx;
        cudaGetSymbolAddress((void**)&gwx, g_wx);
        nt_gemm<1024, false><<<dim3(16, 16), dim3(16, 16)>>>(x, Wih, nullptr, gwx);
    }

    cudaFuncSetAttribute(lstm_attn, cudaFuncAttributeNonPortableClusterSizeAllowed, 1);
    cudaFuncSetAttribute(lstm_attn, cudaFuncAttributeMaxDynamicSharedMemorySize, SMEM_BYTES);

    cudaLaunchConfig_t cfg = {};
    cfg.gridDim = dim3(BB * CL, 1, 1);
    cfg.blockDim = dim3(NTHREADS, 1, 1);
    cfg.dynamicSmemBytes = SMEM_BYTES;
    cfg.stream = 0;
    cudaLaunchAttribute attrs[1];
    attrs[0].id = cudaLaunchAttributeClusterDimension;
    attrs[0].val.clusterDim.x = CL;
    attrs[0].val.clusterDim.y = 1;
    attrs[0].val.clusterDim.z = 1;
    cfg.attrs = attrs;
    cfg.numAttrs = 1;

    cudaLaunchKernelEx(&cfg, lstm_attn, x, sl, W1, W2, b2, Whh, bih, bhh, out);
}

// round 9
// speedup vs baseline: 1.6526x; 1.6526x over previous
#include <cuda_runtime.h>
#include <cstdint>

// Problem constants
#define BB 8
#define TT 128
#define NTHREADS 512

// Output layout (float32, concatenated): outputs[8,128,256], seq_lengths[8],
// hidden[1,8,256], attn[8,128,128]
#define SEQ_OFF     262144
#define HID_OFF     262152
#define ATTN_OFF    264200

// Device scratch
__device__ float g_xw1[1024 * 512];          // x @ W1[:, :E]^T + b1
__device__ float g_wx[1024 * 1024];          // x @ Wih^T
__device__ float g_ep[BB][2][16][128];       // energy partials, double-buffered
__device__ float g_h[BB][2][256];            // replicated h, double-buffered
__device__ unsigned g_fep[BB][TT];           // per-step EP flags (release/acquire)
__device__ unsigned g_fh[BB][TT];            // per-step h flags

// ---------------- SMEM layout (float offsets) ----------------
#define OFF_W1H   0        // [32][256]  W1 h-cols, my 32 k rows
#define OFF_WHH   8192     // [64][256]  Whh rows for my 64 gate rows
#define OFF_WX    24576    // [128][68]  Wx[j][my 64 gate rows] (pitch 68)
#define OFF_HBUF  33280    // [256]  h loaded from global
#define OFF_HPST  33536    // [32]   my hproj slice
#define OFF_HWST  33568    // [64]   my h@Whh rows
#define OFF_BIAS  33632    // [64]
#define OFF_WB    33696    // [128]  softmax weights (local)
#define OFF_GFIN  33824    // [64]   activated gates
#define OFF_CST   33888    // [16]   cell state
#define OFF_SRED  33904    // [16]   softmax-sum warp partials
#define SMEM_FLOATS 33920
#define SMEM_BYTES (SMEM_FLOATS * 4)

// ---------------- helpers ----------------
__device__ __forceinline__ float ldcv(const float* p) {
    float v; asm volatile("ld.global.cv.f32 %0, [%1];" : "=f"(v) : "l"(p)); return v;
}
__device__ __forceinline__ float4 ldcv4(const float* p) {
    float4 v;
    asm volatile("ld.global.cv.v4.f32 {%0,%1,%2,%3}, [%4];"
                 : "=f"(v.x), "=f"(v.y), "=f"(v.z), "=f"(v.w) : "l"(p));
    return v;
}
__device__ __forceinline__ void red_rel(unsigned* p) {
    asm volatile("red.add.release.gpu.u32 [%0], 1;" :: "l"(p) : "memory");
}
__device__ __forceinline__ unsigned ld_acq(const unsigned* p) {
    unsigned v;
    asm volatile("ld.acquire.gpu.u32 %0, [%1];" : "=r"(v) : "l"(p) : "memory");
    return v;
}
__device__ __forceinline__ float wsum(float v) {
    #pragma unroll
    for (int o = 16; o > 0; o >>= 1) v += __shfl_xor_sync(0xffffffffu, v, o);
    return v;
}
// ---- 2-MUFU tanh: e = exp(2x); (e-1)/(e+1). ~1e-6 accurate ----
__device__ __forceinline__ float tanh_m(float x) {
    x = fminf(fmaxf(x, -9.f), 9.f);
    float e = __expf(2.f * x);
    return __fdividef(e - 1.f, e + 1.f);
}
__device__ __forceinline__ float sigmoid_m(float x) {
    return __fdividef(1.f, 1.f + __expf(-x));
}

// ---------------- flag zeroing (runs first every launch/replay) ----------------
__global__ void zero_flags() {
    int i = blockIdx.x * blockDim.x + threadIdx.x;
    if (i < BB * TT) {
        (&g_fep[0][0])[i] = 0u;
        (&g_fh[0][0])[i]  = 0u;
    }
}

// ---------------- precompute GEMMs ----------------
template <int NOUT, bool HASB>
__global__ void nt_gemm(const float* __restrict__ X, const float* __restrict__ W,
                        const float* __restrict__ bias, float* __restrict__ outp) {
    __shared__ float As[64][33];
    __shared__ float Bs[64][33];
    const int m0 = blockIdx.x * 64, n0 = blockIdx.y * 64;
    const int tx = threadIdx.x, ty = threadIdx.y;
    const int tid = ty * 16 + tx;
    float acc[4][4] = {};
    for (int kt = 0; kt < 256; kt += 32) {
        for (int idx = tid; idx < 64 * 32; idx += 256) {
            int rr = idx >> 5, kk = idx & 31;
            As[rr][kk] = X[(m0 + rr) * 256 + kt + kk];
            Bs[rr][kk] = W[(size_t)(n0 + rr) * 256 + kt + kk];
        }
        __syncthreads();
        #pragma unroll
        for (int kk = 0; kk < 32; kk++) {
            float a[4], bv[4];
            #pragma unroll
            for (int i = 0; i < 4; i++) { a[i] = As[ty*4+i][kk]; bv[i] = Bs[tx*4+i][kk]; }
            #pragma unroll
            for (int i = 0; i < 4; i++)
                #pragma unroll
                for (int j = 0; j < 4; j++) acc[i][j] += a[i] * bv[j];
        }
        __syncthreads();
    }
    #pragma unroll
    for (int i = 0; i < 4; i++)
        #pragma unroll
        for (int j = 0; j < 4; j++) {
            int n = n0 + tx*4 + j;
            float v = acc[i][j];
            if (HASB) v += bias[n];
            outp[(size_t)(m0 + ty*4 + i) * NOUT + n] = v;
        }
}

__global__ void xw1_gemm(const float* __restrict__ X, const float* __restrict__ W1,
                         const float* __restrict__ b1) {
    __shared__ float As[64][33];
    __shared__ float Bs[64][33];
    const int m0 = blockIdx.x * 64, n0 = blockIdx.y * 64;
    const int tx = threadIdx.x, ty = threadIdx.y;
    const int tid = ty * 16 + tx;
    float acc[4][4] = {};
    for (int kt = 0; kt < 256; kt += 32) {
        for (int idx = tid; idx < 64 * 32; idx += 256) {
            int rr = idx >> 5, kk = idx & 31;
            As[rr][kk] = X[(m0 + rr) * 256 + kt + kk];
            Bs[rr][kk] = W1[(size_t)(n0 + rr) * 512 + kt + kk];
        }
        __syncthreads();
        #pragma unroll
        for (int kk = 0; kk < 32; kk++) {
            float a[4], bv[4];
            #pragma unroll
            for (int i = 0; i < 4; i++) { a[i] = As[ty*4+i][kk]; bv[i] = Bs[tx*4+i][kk]; }
            #pragma unroll
            for (int i = 0; i < 4; i++)
                #pragma unroll
                for (int j = 0; j < 4; j++) acc[i][j] += a[i] * bv[j];
        }
        __syncthreads();
    }
    #pragma unroll
    for (int i = 0; i < 4; i++)
        #pragma unroll
        for (int j = 0; j < 4; j++) {
            int n = n0 + tx*4 + j;
            g_xw1[(size_t)(m0 + ty*4 + i) * 512 + n] = acc[i][j] + b1[n];
        }
}

// ---------------- persistent recurrence: 128 independent CTAs, L2 flag exchange ----------------
__global__ void __launch_bounds__(NTHREADS, 1)
lstm_attn(const float* __restrict__ x, const int* __restrict__ seqlen,
          const float* __restrict__ W1, const float* __restrict__ W2,
          const float* __restrict__ b2w, const float* __restrict__ Whh,
          const float* __restrict__ bih, const float* __restrict__ bhh,
          float* __restrict__ out) {
    extern __shared__ float sm[];
    const int tid = threadIdx.x;
    const int w = tid >> 5, lane = tid & 31;
    const int r = blockIdx.x & 15;
    const int b = blockIdx.x >> 4;
    const int len = seqlen[b];
    const float b2v = b2w[0];

    // ---- prologue: weight slices ----
    for (int idx = tid; idx < 32 * 256; idx += NTHREADS) {          // W1 h-cols, k rows [32r,32r+32)
        int row = idx >> 8, d = idx & 255;
        sm[OFF_W1H + idx] = W1[(size_t)(32 * r + row) * 512 + 256 + d];
    }
    for (int idx = tid; idx < 64 * 256; idx += NTHREADS) {          // Whh rows for my gates
        int q = idx >> 8, d = idx & 255;
        int gate = q >> 4, i = q & 15;
        sm[OFF_WHH + idx] = Whh[(size_t)(gate * 256 + 16 * r + i) * 256 + d];
    }
    for (int idx = tid; idx < 128 * 64; idx += NTHREADS) {          // Wx[j][my 64 rows], pitch 68
        int j = idx >> 6, q = idx & 63;
        sm[OFF_WX + j * 68 + q] =
            g_wx[(size_t)(b * 128 + j) * 1024 + ((q >> 4) << 8) + 16 * r + (q & 15)];
    }
    if (tid < 64) {
        int gate = tid >> 4, i = tid & 15;
        int row = gate * 256 + 16 * r + i;
        sm[OFF_BIAS + tid] = bih[row] + bhh[row];
        sm[OFF_HWST + tid] = 0.f;                      // t=0: h=0 -> h@Whh = 0
    }
    if (tid < 32) sm[OFF_HPST + tid] = 0.f;
    if (tid < 16) sm[OFF_CST + tid] = 0.f;
    if (r == 0 && tid == 0) out[SEQ_OFF + b] = (float)len;

    // per-thread loop-invariant registers: my 8 xw1 values and 8 W2 values
    const int jE = tid >> 2, qE = tid & 3;
    float xwr[8], w2r[8];
    {
        const float* src = g_xw1 + (size_t)(b * 128 + jE) * 512 + 32 * r + qE * 8;
        const float* w2s = W2 + 32 * r + qE * 8;
        #pragma unroll
        for (int i = 0; i < 8; i++) { xwr[i] = src[i]; w2r[i] = w2s[i]; }
    }
    __syncthreads();

    for (int t = 0; t < TT; t++) {
        const int slot = t & 1;
        const bool active = t < len;

        // ---- h phase (t>=1): wait flag, load replicated h from L2, compute P1 ----
        if (t > 0) {
            if (tid == 0) { while (ld_acq(&g_fh[b][t - 1]) < 16u) {} }
            __syncthreads();
            if (tid < 64) {
                float4 v = ldcv4(&g_h[b][slot][tid * 4]);
                *(float4*)(sm + OFF_HBUF + tid * 4) = v;
            }
            __syncthreads();
            // P1: hproj (32 rows) + h@Whh (64 rows): 16 warps x 6 rows
            const float* hb = sm + OFF_HBUF;
            float4 h0 = *(const float4*)(hb + lane * 8);
            float4 h1 = *(const float4*)(hb + lane * 8 + 4);
            #pragma unroll
            for (int rr = 0; rr < 6; rr++) {
                int row = w * 6 + rr;
                const float* wr = (row < 32) ? (sm + OFF_W1H + row * 256)
                                             : (sm + OFF_WHH + (row - 32) * 256);
                float4 a0 = *(const float4*)(wr + lane * 8);
                float4 a1 = *(const float4*)(wr + lane * 8 + 4);
                float acc = a0.x*h0.x + a0.y*h0.y + a0.z*h0.z + a0.w*h0.w
                          + a1.x*h1.x + a1.y*h1.y + a1.z*h1.z + a1.w*h1.w;
                acc = wsum(acc);
                if (lane == 0) {
                    if (row < 32) sm[OFF_HPST + row] = acc;
                    else          sm[OFF_HWST + row - 32] = acc;
                }
            }
            __syncthreads();
        }

        // ---- P2: energy partials (8 tanh/thread); write row to L2; publish ----
        {
            const float4* hp4 = (const float4*)(sm + OFF_HPST + qE * 8);
            float4 hpa = hp4[0], hpb = hp4[1];
            const float hp[8] = {hpa.x, hpa.y, hpa.z, hpa.w, hpb.x, hpb.y, hpb.z, hpb.w};
            float acc = 0.f;
            #pragma unroll
            for (int i = 0; i < 8; i++)
                acc = fmaf(tanh_m(xwr[i] + hp[i]), w2r[i], acc);
            acc += __shfl_xor_sync(0xffffffffu, acc, 1);
            acc += __shfl_xor_sync(0xffffffffu, acc, 2);
            if (qE == 0) g_ep[b][slot][r][jE] = acc;
        }
        __syncthreads();
        if (tid == 0) red_rel(&g_fep[b][t]);

        // ---- P3: wait all partials; read from L2; softmax locally ----
        if (tid == 0) { while (ld_acq(&g_fep[b][t]) < 16u) {} }
        __syncthreads();
        float ex = 0.f;
        {
            const float* epb = &g_ep[b][slot][0][0];
            float s = ldcv(epb + (4*qE + 0) * 128 + jE) + ldcv(epb + (4*qE + 1) * 128 + jE)
                    + ldcv(epb + (4*qE + 2) * 128 + jE) + ldcv(epb + (4*qE + 3) * 128 + jE);
            s += __shfl_xor_sync(0xffffffffu, s, 1);
            s += __shfl_xor_sync(0xffffffffu, s, 2);
            if (qE == 0)
                ex = (jE < len) ? __expf(tanh_m(s + b2v)) : 0.f;  // energies in [-1,1]
        }
        float wp = wsum(ex);
        if (lane == 0) sm[OFF_SRED + w] = wp;
        __syncthreads();
        {
            const float4* sr = (const float4*)(sm + OFF_SRED);
            float4 a = sr[0], c = sr[1], d = sr[2], e4 = sr[3];
            float S = (a.x+a.y+a.z+a.w) + (c.x+c.y+c.z+c.w)
                    + (d.x+d.y+d.z+d.w) + (e4.x+e4.y+e4.z+e4.w);
            float Sinv = __fdividef(1.f, S);
            if (qE == 0) {
                float wv = active ? ex * Sinv : 0.f;
                sm[OFF_WB + jE] = wv;
                if ((jE >> 3) == r)
                    out[ATTN_OFF + (size_t)(b * 128 + t) * 128 + jE] = wv;
            }
        }
        __syncthreads();

        // ---- P4: gates from Wx: row q = tid>>3, jq = tid&7 ----
        {
            int q = tid >> 3, jq = tid & 7;
            const float* wx = sm + OFF_WX + q;
            float acc = 0.f;
            #pragma unroll
            for (int jj = 0; jj < 16; jj++) {
                int j = jq + 8 * jj;
                acc = fmaf(sm[OFF_WB + j], wx[j * 68], acc);
            }
            acc += __shfl_xor_sync(0xffffffffu, acc, 1);
            acc += __shfl_xor_sync(0xffffffffu, acc, 2);
            acc += __shfl_xor_sync(0xffffffffu, acc, 4);
            if (jq == 0) {
                acc += sm[OFF_HWST + q] + sm[OFF_BIAS + q];
                sm[OFF_GFIN + q] = ((q >> 4) == 2) ? tanh_m(acc) : sigmoid_m(acc);
            }
        }
        __syncthreads();

        // ---- P5: LSTM update; write outputs; publish h(t+1) ----
        if (tid < 16) {
            float c = sm[OFF_GFIN + 16 + tid] * sm[OFF_CST + tid]
                    + sm[OFF_GFIN + tid] * sm[OFF_GFIN + 32 + tid];
            sm[OFF_CST + tid] = c;
            float hn = sm[OFF_GFIN + 48 + tid] * tanh_m(c);
            out[(size_t)(b * 128 + t) * 256 + 16 * r + tid] = active ? hn : 0.f;
            if (t == len - 1) out[HID_OFF + b * 256 + 16 * r + tid] = hn;
            if (t < TT - 1) g_h[b][(t + 1) & 1][16 * r + tid] = hn;
            __syncwarp(0x0000ffffu);
            if (tid == 0 && t < TT - 1) red_rel(&g_fh[b][t]);
        }
        __syncthreads();
    }
}

// ---------------- host launch ----------------
extern "C" void kernel_launch(void* const* d_in, const int* in_sizes, int n_in,
                              void* d_out, int out_size) {
    const float* x   = (const float*)d_in[0];
    const int*   sl  = (const int*)  d_in[1];
    const float* W1  = (const float*)d_in[2];
    const float* b1  = (const float*)d_in[3];
    const float* W2  = (const float*)d_in[4];
    const float* b2  = (const float*)d_in[5];
    const float* Wih = (const float*)d_in[6];
    const float* Whh = (const float*)d_in[7];
    const float* bih = (const float*)d_in[8];
    const float* bhh = (const float*)d_in[9];
    float* out = (float*)d_out;

    zero_flags<<<2, 512>>>();
    xw1_gemm<<<dim3(16, 8), dim3(16, 16)>>>(x, W1, b1);
    {
        float* gwx;
        cudaGetSymbolAddress((void**)&gwx, g_wx);
        nt_gemm<1024, false><<<dim3(16, 16), dim3(16, 16)>>>(x, Wih, nullptr, gwx);
    }

    cudaFuncSetAttribute(lstm_attn, cudaFuncAttributeMaxDynamicSharedMemorySize, SMEM_BYTES);
    lstm_attn<<<BB * 16, NTHREADS, SMEM_BYTES>>>(x, sl, W1, W2, b2, Whh, bih, bhh, out);
}